// round 2
// baseline (speedup 1.0000x reference)
#include <cuda_runtime.h>

#define TPB 512
#define SCALE 0.17677669529663687f

// ---------------------------------------------------------------------------
// B=2, C=96, D=H=W=64, WS=8 -> N=64 tokens/window, HEADS=3, HD=32
// 3 branches x 8192 windows. One window per 512-thread block, fully fused.
// ---------------------------------------------------------------------------

__device__ __align__(16) float g_bias[3 * 3 * 4096];   // expanded rpb bias

__global__ void bias_expand_kernel(const float* __restrict__ table,
                                   const int* __restrict__ idx) {
    int i = blockIdx.x * 256 + threadIdx.x;            // 36864 total
    if (i >= 3 * 3 * 4096) return;
    int br = i / 12288;
    int h  = (i / 4096) % 3;
    int nm = i & 4095;
    g_bias[i] = table[(br * 225 + idx[nm]) * 3 + h];
}

// packed f32x2 FMA (FFMA2)
union f2u { float2 f; unsigned long long u; };
__device__ __forceinline__ void fma2(f2u& d, const f2u a, const f2u b) {
    asm("fma.rn.f32x2 %0, %1, %2, %0;" : "+l"(d.u) : "l"(a.u), "l"(b.u));
}
__device__ __forceinline__ f2u bcast(float a) { f2u r; r.f = make_float2(a, a); return r; }
__device__ __forceinline__ f2u ld2s(const float* p) { f2u r; r.f = *(const float2*)p; return r; }
__device__ __forceinline__ f2u ld2g(const float* p) { f2u r; r.f = __ldg((const float2*)p); return r; }

__device__ __forceinline__ int x_off(int br, int b, int c, int s, int p, int q) {
    int d, h, w;
    if (br == 0)      { d = s; h = p; w = q; }   // image=(b,d), spatial (h,w)
    else if (br == 1) { d = q; h = p; w = s; }   // image=(b,w), spatial (h,d)
    else              { d = p; h = s; w = q; }   // image=(b,h), spatial (d,w)
    return (((b * 96 + c) * 64 + d) * 64 + h) * 64 + w;
}

// smem layout (float offsets)
#define XS   0        // [64][97]  window input; reused as attn output
#define QS   6208     // [64][97]  q (pre-scaled)
#define KS   12416    // [96][66]  k transposed: ks[o][tok]
#define VS   18752    // [64][96]  v
#define WST  24896    // [96][96]  staged weight tile wst[c][o]
#define AS   34112    // [64][65]  attention scores
#define INVS 38272    // [96]
#define SHS  38368    // [96]
#define SMEM_FLOATS 38464

template<bool ATOMIC>
__global__ __launch_bounds__(TPB, 1)
void swin_win_kernel(
    const float* __restrict__ x,
    const float* __restrict__ qkv_w, const float* __restrict__ qkv_b,
    const float* __restrict__ proj_w, const float* __restrict__ proj_b,
    const float* __restrict__ bn_g, const float* __restrict__ bn_b,
    const float* __restrict__ bn_m, const float* __restrict__ bn_v,
    float* __restrict__ out, int br_base)
{
    extern __shared__ float sm[];
    float* xs   = sm + XS;
    float* qs   = sm + QS;
    float* ks   = sm + KS;
    float* vs   = sm + VS;
    float* wst  = sm + WST;
    float* as_  = sm + AS;
    float* invs = sm + INVS;
    float* shs  = sm + SHS;

    const int tid = threadIdx.x;
    const int bid = blockIdx.x;
    const int br  = br_base + (bid >> 13);
    const int wid = bid & 8191;
    const int g   = wid & 127;          // image index inner -> L2 line sharing
    const int win = wid >> 7;
    const int wi  = win >> 3;
    const int wj  = win & 7;
    const int b   = g >> 6;
    const int s   = g & 63;

    if (tid < 96) {
        float inv = bn_g[br * 96 + tid] * rsqrtf(bn_v[br * 96 + tid] + 1e-5f);
        invs[tid] = inv;
        shs[tid]  = bn_b[br * 96 + tid] - bn_m[br * 96 + tid] * inv;
    }

    // load window: xs[tok][c]
    for (int i = tid; i < 6144; i += TPB) {
        int c   = i >> 6;
        int tok = i & 63;
        int p = wi * 8 + (tok >> 3), q = wj * 8 + (tok & 7);
        xs[tok * 97 + c] = x[x_off(br, b, c, s, p, q)];
    }
    __syncthreads();

    const int tn = tid >> 4;   // token-pair group 0..31 (2 tokens)
    const int to = tid & 15;   // out-chan group 0..15 (6 outs)

    // ---- qkv GEMM: three 96-wide passes ---------------------------------
    #pragma unroll
    for (int pass = 0; pass < 3; ++pass) {
        const int obase = pass * 96;
        for (int i = tid; i < 9216; i += TPB) {
            int o = i / 96, c = i - o * 96;
            wst[c * 96 + o] = qkv_w[(br * 288 + obase + o) * 96 + c];
        }
        __syncthreads();

        f2u acc[2][3];
        #pragma unroll
        for (int jp = 0; jp < 3; ++jp) {
            float b0 = qkv_b[br * 288 + obase + to * 6 + jp * 2];
            float b1 = qkv_b[br * 288 + obase + to * 6 + jp * 2 + 1];
            acc[0][jp].f = make_float2(b0, b1);
            acc[1][jp].f = make_float2(b0, b1);
        }
        #pragma unroll 4
        for (int c = 0; c < 96; ++c) {
            f2u av0 = bcast(xs[(tn * 2 + 0) * 97 + c]);
            f2u av1 = bcast(xs[(tn * 2 + 1) * 97 + c]);
            f2u w0 = ld2s(wst + c * 96 + to * 6);
            f2u w1 = ld2s(wst + c * 96 + to * 6 + 2);
            f2u w2 = ld2s(wst + c * 96 + to * 6 + 4);
            fma2(acc[0][0], av0, w0); fma2(acc[0][1], av0, w1); fma2(acc[0][2], av0, w2);
            fma2(acc[1][0], av1, w0); fma2(acc[1][1], av1, w1); fma2(acc[1][2], av1, w2);
        }
        #pragma unroll
        for (int i = 0; i < 2; ++i) {
            int tok = tn * 2 + i;
            #pragma unroll
            for (int jp = 0; jp < 3; ++jp) {
                int o = to * 6 + jp * 2;
                if (pass == 0) {                      // q, pre-scaled
                    qs[tok * 97 + o]     = acc[i][jp].f.x * SCALE;
                    qs[tok * 97 + o + 1] = acc[i][jp].f.y * SCALE;
                } else if (pass == 1) {               // k transposed
                    ks[(o)     * 66 + tok] = acc[i][jp].f.x;
                    ks[(o + 1) * 66 + tok] = acc[i][jp].f.y;
                } else {                              // v
                    *(float2*)&vs[tok * 96 + o] = acc[i][jp].f;
                }
            }
        }
        __syncthreads();
    }

    // ---- attention per head ---------------------------------------------
    #pragma unroll
    for (int h = 0; h < 3; ++h) {
        // scores: s[n][m] = <q_n, k_m> + bias
        {
            const int ng = tid & 31;          // n in {ng, ng+32}
            const int mg = tid >> 5;          // m = mg*4 + 0..3
            f2u sacc[2][2];
            #pragma unroll
            for (int i = 0; i < 2; ++i)
                #pragma unroll
                for (int kp = 0; kp < 2; ++kp) sacc[i][kp].f = make_float2(0.f, 0.f);
            const float* q0p = qs + (ng)      * 97 + h * 32;
            const float* q1p = qs + (ng + 32) * 97 + h * 32;
            #pragma unroll 4
            for (int d = 0; d < 32; ++d) {
                f2u k0 = ld2s(ks + (h * 32 + d) * 66 + mg * 4);
                f2u k1 = ld2s(ks + (h * 32 + d) * 66 + mg * 4 + 2);
                f2u qv0 = bcast(q0p[d]);
                f2u qv1 = bcast(q1p[d]);
                fma2(sacc[0][0], qv0, k0); fma2(sacc[0][1], qv0, k1);
                fma2(sacc[1][0], qv1, k0); fma2(sacc[1][1], qv1, k1);
            }
            const float* bb = g_bias + (br * 3 + h) * 4096;
            #pragma unroll
            for (int i = 0; i < 2; ++i) {
                int n = ng + 32 * i;
                #pragma unroll
                for (int kp = 0; kp < 2; ++kp) {
                    int m = mg * 4 + kp * 2;
                    f2u bv = ld2g(bb + n * 64 + m);
                    as_[n * 65 + m]     = sacc[i][kp].f.x + bv.f.x;
                    as_[n * 65 + m + 1] = sacc[i][kp].f.y + bv.f.y;
                }
            }
        }
        __syncthreads();

        // softmax: 8 lanes per row
        {
            const int row  = tid >> 3;
            const int lane = tid & 7;
            float* r = as_ + row * 65;
            float v[8];
            float mx = -1e30f;
            #pragma unroll
            for (int t = 0; t < 8; ++t) { v[t] = r[lane + t * 8]; mx = fmaxf(mx, v[t]); }
            mx = fmaxf(mx, __shfl_xor_sync(0xffffffff, mx, 4));
            mx = fmaxf(mx, __shfl_xor_sync(0xffffffff, mx, 2));
            mx = fmaxf(mx, __shfl_xor_sync(0xffffffff, mx, 1));
            float sum = 0.f;
            #pragma unroll
            for (int t = 0; t < 8; ++t) { v[t] = __expf(v[t] - mx); sum += v[t]; }
            sum += __shfl_xor_sync(0xffffffff, sum, 4);
            sum += __shfl_xor_sync(0xffffffff, sum, 2);
            sum += __shfl_xor_sync(0xffffffff, sum, 1);
            float rs = 1.f / sum;
            #pragma unroll
            for (int t = 0; t < 8; ++t) r[lane + t * 8] = v[t] * rs;
        }
        __syncthreads();

        // out = attn @ v  -> xs[n][h*32 + d]   (xs input is dead)
        {
            const int ng = tid & 31;          // n in {ng, ng+32}
            const int dg = tid >> 5;          // d = dg*2 + {0,1}
            f2u oacc[2];
            oacc[0].f = make_float2(0.f, 0.f);
            oacc[1].f = make_float2(0.f, 0.f);
            #pragma unroll 4
            for (int m = 0; m < 64; ++m) {
                f2u vv = ld2s(vs + m * 96 + h * 32 + dg * 2);
                f2u a0 = bcast(as_[(ng)      * 65 + m]);
                f2u a1 = bcast(as_[(ng + 32) * 65 + m]);
                fma2(oacc[0], a0, vv);
                fma2(oacc[1], a1, vv);
            }
            int col = h * 32 + dg * 2;
            xs[(ng)      * 97 + col]     = oacc[0].f.x;
            xs[(ng)      * 97 + col + 1] = oacc[0].f.y;
            xs[(ng + 32) * 97 + col]     = oacc[1].f.x;
            xs[(ng + 32) * 97 + col + 1] = oacc[1].f.y;
        }
        __syncthreads();
    }

    // ---- proj + BN + LeakyReLU + store ----------------------------------
    for (int i = tid; i < 9216; i += TPB) {
        int co = i / 96, ci = i - co * 96;
        wst[ci * 96 + co] = proj_w[(br * 96 + co) * 96 + ci];
    }
    __syncthreads();

    {
        f2u acc[2][3];
        #pragma unroll
        for (int jp = 0; jp < 3; ++jp) {
            float b0 = proj_b[br * 96 + to * 6 + jp * 2];
            float b1 = proj_b[br * 96 + to * 6 + jp * 2 + 1];
            acc[0][jp].f = make_float2(b0, b1);
            acc[1][jp].f = make_float2(b0, b1);
        }
        #pragma unroll 4
        for (int ci = 0; ci < 96; ++ci) {
            f2u av0 = bcast(xs[(tn * 2 + 0) * 97 + ci]);
            f2u av1 = bcast(xs[(tn * 2 + 1) * 97 + ci]);
            f2u w0 = ld2s(wst + ci * 96 + to * 6);
            f2u w1 = ld2s(wst + ci * 96 + to * 6 + 2);
            f2u w2 = ld2s(wst + ci * 96 + to * 6 + 4);
            fma2(acc[0][0], av0, w0); fma2(acc[0][1], av0, w1); fma2(acc[0][2], av0, w2);
            fma2(acc[1][0], av1, w0); fma2(acc[1][1], av1, w1); fma2(acc[1][2], av1, w2);
        }
        #pragma unroll
        for (int i = 0; i < 2; ++i) {
            int n  = tn * 2 + i;
            int p = wi * 8 + (n >> 3), q = wj * 8 + (n & 7);
            #pragma unroll
            for (int jp = 0; jp < 3; ++jp) {
                #pragma unroll
                for (int t = 0; t < 2; ++t) {
                    int co = to * 6 + jp * 2 + t;
                    float a = t ? acc[i][jp].f.y : acc[i][jp].f.x;
                    float yn = a * invs[co] + shs[co];
                    yn = (yn >= 0.f) ? yn : 0.01f * yn;
                    int off = x_off(br, b, co, s, p, q);
                    if (ATOMIC) atomicAdd(&out[off], yn);
                    else        out[off] = yn;
                }
            }
        }
    }
}

extern "C" void kernel_launch(void* const* d_in, const int* in_sizes, int n_in,
                              void* d_out, int out_size)
{
    (void)in_sizes; (void)n_in; (void)out_size;
    const float* x         = (const float*)d_in[0];
    const float* qkv_w     = (const float*)d_in[1];
    const float* qkv_b     = (const float*)d_in[2];
    const float* proj_w    = (const float*)d_in[3];
    const float* proj_b    = (const float*)d_in[4];
    const float* rpb_table = (const float*)d_in[5];
    const float* bn_g      = (const float*)d_in[6];
    const float* bn_b      = (const float*)d_in[7];
    const float* bn_m      = (const float*)d_in[8];
    const float* bn_v      = (const float*)d_in[9];
    const int*   rpb_index = (const int*)d_in[10];
    float* out = (float*)d_out;

    bias_expand_kernel<<<144, 256>>>(rpb_table, rpb_index);

    const int smem = SMEM_FLOATS * 4;
    cudaFuncSetAttribute(swin_win_kernel<false>,
                         cudaFuncAttributeMaxDynamicSharedMemorySize, smem);
    cudaFuncSetAttribute(swin_win_kernel<true>,
                         cudaFuncAttributeMaxDynamicSharedMemorySize, smem);

    // Branch 0: plain stores (full coverage kills 0xAA poison)
    swin_win_kernel<false><<<8192, TPB, smem>>>(
        x, qkv_w, qkv_b, proj_w, proj_b, bn_g, bn_b, bn_m, bn_v, out, 0);
    // Branches 1 & 2: accumulate
    swin_win_kernel<true><<<16384, TPB, smem>>>(
        x, qkv_w, qkv_b, proj_w, proj_b, bn_g, bn_b, bn_m, bn_v, out, 1);
}

// round 3
// speedup vs baseline: 1.7444x; 1.7444x over previous
#include <cuda_runtime.h>

#define TPB 256
#define SCALE 0.17677669529663687f

// ---------------------------------------------------------------------------
// B=2, C=96, D=H=W=64, WS=8 -> N=64 tokens/window, HEADS=3, HD=32
// 3 branches x 8192 windows. One window per 256-thread block, fully fused.
// FFMA2 (fma.rn.f32x2) paired along the REDUCTION dim: both operands are
// natural float2 loads; halves summed once at the end of each dot product.
// ---------------------------------------------------------------------------

__device__ __align__(16) float g_bias[3 * 3 * 4096];   // [br][h][n][m]

__global__ void bias_expand_kernel(const float* __restrict__ table,
                                   const int* __restrict__ idx) {
    int i = blockIdx.x * 256 + threadIdx.x;            // 36864 total
    if (i >= 36864) return;
    int br = i / 12288;
    int h  = (i >> 12) % 3;
    int nm = i & 4095;
    g_bias[i] = table[(br * 225 + idx[nm]) * 3 + h];
}

union f2u { float2 f; unsigned long long u; };
__device__ __forceinline__ void fma2(f2u& d, f2u a, f2u b) {
    asm("fma.rn.f32x2 %0, %1, %2, %0;" : "+l"(d.u) : "l"(a.u), "l"(b.u));
}
__device__ __forceinline__ f2u ld2(const float* p) { f2u r; r.f = *(const float2*)p; return r; }

__device__ __forceinline__ int x_off(int br, int b, int c, int s, int p, int q) {
    int d, h, w;
    if (br == 0)      { d = s; h = p; w = q; }   // image=(b,d), spatial (h,w)
    else if (br == 1) { d = q; h = p; w = s; }   // image=(b,w), spatial (h,d)
    else              { d = p; h = s; w = q; }   // image=(b,h), spatial (d,w)
    return (((b * 96 + c) * 64 + d) * 64 + h) * 64 + w;
}

// smem layout (float offsets), total 28608 floats = 111.8 KB -> 2 CTAs/SM
#define XS   0        // [64][98]  window input, row-major [tok][c]
#define QQ   6272     // [64][34]  q (per head)
#define KK   8448     // [64][34]  k (per head)
#define VT   10624    // [32][66]  v transposed [d][tok] (per head)
#define OS   12736    // [64][98]  attention output
#define WST  19008    // [96][98]  staged weights [o][c]  (union with AS_)
#define AS_  19008    // [64][66]  scores (alive only after GEMM of same head)
#define INVS 28416    // [96]
#define SHS  28512    // [96]
#define SMEM_FLOATS 28608

template<bool ATOMIC>
__global__ __launch_bounds__(TPB, 2)
void swin_win_kernel(
    const float* __restrict__ x,
    const float* __restrict__ qkv_w, const float* __restrict__ qkv_b,
    const float* __restrict__ proj_w, const float* __restrict__ proj_b,
    const float* __restrict__ bn_g, const float* __restrict__ bn_b,
    const float* __restrict__ bn_m, const float* __restrict__ bn_v,
    float* __restrict__ out, int br_base)
{
    extern __shared__ float sm[];
    float* xs   = sm + XS;
    float* qq   = sm + QQ;
    float* kk   = sm + KK;
    float* vt   = sm + VT;
    float* os   = sm + OS;
    float* wst  = sm + WST;
    float* as_  = sm + AS_;
    float* invs = sm + INVS;
    float* shs  = sm + SHS;

    const int tid = threadIdx.x;
    const int bid = blockIdx.x;
    const int br  = br_base + (bid >> 13);
    const int wid = bid & 8191;
    const int g   = wid & 127;          // image index inner -> L2 line sharing
    const int win = wid >> 7;
    const int wi  = win >> 3;
    const int wj  = win & 7;
    const int b   = g >> 6;
    const int s   = g & 63;

    if (tid < 96) {
        float inv = bn_g[br * 96 + tid] * rsqrtf(bn_v[br * 96 + tid] + 1e-5f);
        invs[tid] = inv;
        shs[tid]  = bn_b[br * 96 + tid] - bn_m[br * 96 + tid] * inv;
    }

    // load window: xs[tok][c]  (tok fastest -> coalesced gmem, stride-1-ish STS)
    for (int i = tid; i < 6144; i += TPB) {
        int c   = i >> 6;
        int tok = i & 63;
        int p = wi * 8 + (tok >> 3), q = wj * 8 + (tok & 7);
        xs[tok * 98 + c] = x[x_off(br, b, c, s, p, q)];
    }
    __syncthreads();

    const int tn = tid >> 4;   // token group (4 tokens)
    const int to = tid & 15;   // out-chan group (6 outs)

    // =================== per-head: qkv GEMM -> attention ===================
    for (int h = 0; h < 3; ++h) {
        // stage this head's 96 weight rows [u][c] (u = mat*32+oo packed)
        for (int i = tid; i < 9216; i += TPB) {
            int u = i / 96, c = i - u * 96;
            int grow = br * 288 + (u >> 5) * 96 + h * 32 + (u & 31);
            wst[u * 98 + c] = qkv_w[grow * 96 + c];
        }
        __syncthreads();

        // ---- GEMM1: out[tok][u] = xs[tok][:] . w[u][:] + bias --------------
        {
            f2u acc[4][6];
            #pragma unroll
            for (int j = 0; j < 6; ++j) {
                int u = to * 6 + j;
                float bb = qkv_b[br * 288 + (u >> 5) * 96 + h * 32 + (u & 31)];
                #pragma unroll
                for (int i = 0; i < 4; ++i) acc[i][j].f = make_float2(bb, 0.f);
            }
            #pragma unroll 4
            for (int c = 0; c < 96; c += 2) {
                f2u av[4], wv[6];
                #pragma unroll
                for (int i = 0; i < 4; ++i) av[i] = ld2(xs + (tn * 4 + i) * 98 + c);
                #pragma unroll
                for (int j = 0; j < 6; ++j) wv[j] = ld2(wst + (to * 6 + j) * 98 + c);
                #pragma unroll
                for (int i = 0; i < 4; ++i)
                    #pragma unroll
                    for (int j = 0; j < 6; ++j) fma2(acc[i][j], av[i], wv[j]);
            }
            #pragma unroll
            for (int i = 0; i < 4; ++i) {
                int tok = tn * 4 + i;
                #pragma unroll
                for (int j = 0; j < 6; ++j) {
                    int u = to * 6 + j;
                    float r = acc[i][j].f.x + acc[i][j].f.y;
                    if (u < 32)      qq[tok * 34 + u] = r;
                    else if (u < 64) kk[tok * 34 + (u - 32)] = r;
                    else             vt[(u - 64) * 66 + tok] = r;
                }
            }
        }
        __syncthreads();

        // ---- scores: s[n][m] = <q_n,k_m>*scale + bias ----------------------
        // n = ng + 16i, m = mg + 16k  (row spreading keeps LDS conflict-free)
        {
            const int ng = tid & 15;
            const int mg = tid >> 4;
            f2u sacc[4][4];
            #pragma unroll
            for (int i = 0; i < 4; ++i)
                #pragma unroll
                for (int k = 0; k < 4; ++k) sacc[i][k].f = make_float2(0.f, 0.f);
            #pragma unroll 4
            for (int d = 0; d < 32; d += 2) {
                f2u qv[4], kv[4];
                #pragma unroll
                for (int i = 0; i < 4; ++i) qv[i] = ld2(qq + (ng + 16 * i) * 34 + d);
                #pragma unroll
                for (int k = 0; k < 4; ++k) kv[k] = ld2(kk + (mg + 16 * k) * 34 + d);
                #pragma unroll
                for (int i = 0; i < 4; ++i)
                    #pragma unroll
                    for (int k = 0; k < 4; ++k) fma2(sacc[i][k], qv[i], kv[k]);
            }
            const float* bb = g_bias + (br * 3 + h) * 4096;
            #pragma unroll
            for (int i = 0; i < 4; ++i) {
                int n = ng + 16 * i;
                #pragma unroll
                for (int k = 0; k < 4; ++k) {
                    int m = mg + 16 * k;
                    as_[n * 66 + m] = (sacc[i][k].f.x + sacc[i][k].f.y) * SCALE
                                      + __ldg(bb + n * 64 + m);
                }
            }
        }
        __syncthreads();

        // ---- softmax: 4 lanes per row --------------------------------------
        {
            const int row  = tid >> 2;
            const int lane = tid & 3;
            float* r = as_ + row * 66 + lane * 16;
            float v[16];
            float mx = -1e30f;
            #pragma unroll
            for (int t = 0; t < 16; ++t) { v[t] = r[t]; mx = fmaxf(mx, v[t]); }
            mx = fmaxf(mx, __shfl_xor_sync(0xffffffff, mx, 2));
            mx = fmaxf(mx, __shfl_xor_sync(0xffffffff, mx, 1));
            float sum = 0.f;
            #pragma unroll
            for (int t = 0; t < 16; ++t) { v[t] = __expf(v[t] - mx); sum += v[t]; }
            sum += __shfl_xor_sync(0xffffffff, sum, 2);
            sum += __shfl_xor_sync(0xffffffff, sum, 1);
            float rs = 1.f / sum;
            #pragma unroll
            for (int t = 0; t < 16; ++t) r[t] = v[t] * rs;
        }
        __syncthreads();

        // ---- out = attn @ v  -> os[n][h*32+dd] -----------------------------
        {
            const int ng = tid & 31;   // rows {ng, ng+32}
            const int dg = tid >> 5;   // dd = dg*4 + jj
            f2u oacc[2][4];
            #pragma unroll
            for (int r2 = 0; r2 < 2; ++r2)
                #pragma unroll
                for (int jj = 0; jj < 4; ++jj) oacc[r2][jj].f = make_float2(0.f, 0.f);
            #pragma unroll 4
            for (int m = 0; m < 64; m += 2) {
                f2u a0 = ld2(as_ + ng * 66 + m);
                f2u a1 = ld2(as_ + (ng + 32) * 66 + m);
                f2u vv[4];
                #pragma unroll
                for (int jj = 0; jj < 4; ++jj) vv[jj] = ld2(vt + (dg * 4 + jj) * 66 + m);
                #pragma unroll
                for (int jj = 0; jj < 4; ++jj) {
                    fma2(oacc[0][jj], a0, vv[jj]);
                    fma2(oacc[1][jj], a1, vv[jj]);
                }
            }
            #pragma unroll
            for (int r2 = 0; r2 < 2; ++r2) {
                int n = ng + 32 * r2;
                #pragma unroll
                for (int jj = 0; jj < 4; ++jj)
                    os[n * 98 + h * 32 + dg * 4 + jj] = oacc[r2][jj].f.x + oacc[r2][jj].f.y;
            }
        }
        __syncthreads();
    }

    // =================== proj + BN + LeakyReLU + store =====================
    for (int i = tid; i < 9216; i += TPB) {
        int u = i / 96, c = i - u * 96;
        wst[u * 98 + c] = proj_w[(br * 96 + u) * 96 + c];
    }
    __syncthreads();

    {
        f2u acc[4][6];
        #pragma unroll
        for (int j = 0; j < 6; ++j) {
            float bb = proj_b[br * 96 + to * 6 + j];
            #pragma unroll
            for (int i = 0; i < 4; ++i) acc[i][j].f = make_float2(bb, 0.f);
        }
        #pragma unroll 4
        for (int c = 0; c < 96; c += 2) {
            f2u av[4], wv[6];
            #pragma unroll
            for (int i = 0; i < 4; ++i) av[i] = ld2(os + (tn * 4 + i) * 98 + c);
            #pragma unroll
            for (int j = 0; j < 6; ++j) wv[j] = ld2(wst + (to * 6 + j) * 98 + c);
            #pragma unroll
            for (int i = 0; i < 4; ++i)
                #pragma unroll
                for (int j = 0; j < 6; ++j) fma2(acc[i][j], av[i], wv[j]);
        }
        #pragma unroll
        for (int i = 0; i < 4; ++i) {
            int tok = tn * 4 + i;
            int p = wi * 8 + (tok >> 3), q = wj * 8 + (tok & 7);
            #pragma unroll
            for (int j = 0; j < 6; ++j) {
                int co = to * 6 + j;
                float r  = acc[i][j].f.x + acc[i][j].f.y;
                float yn = r * invs[co] + shs[co];
                yn = (yn >= 0.f) ? yn : 0.01f * yn;
                int off = x_off(br, b, co, s, p, q);
                if (ATOMIC) atomicAdd(&out[off], yn);
                else        out[off] = yn;
            }
        }
    }
}

extern "C" void kernel_launch(void* const* d_in, const int* in_sizes, int n_in,
                              void* d_out, int out_size)
{
    (void)in_sizes; (void)n_in; (void)out_size;
    const float* x         = (const float*)d_in[0];
    const float* qkv_w     = (const float*)d_in[1];
    const float* qkv_b     = (const float*)d_in[2];
    const float* proj_w    = (const float*)d_in[3];
    const float* proj_b    = (const float*)d_in[4];
    const float* rpb_table = (const float*)d_in[5];
    const float* bn_g      = (const float*)d_in[6];
    const float* bn_b      = (const float*)d_in[7];
    const float* bn_m      = (const float*)d_in[8];
    const float* bn_v      = (const float*)d_in[9];
    const int*   rpb_index = (const int*)d_in[10];
    float* out = (float*)d_out;

    bias_expand_kernel<<<144, 256>>>(rpb_table, rpb_index);

    const int smem = SMEM_FLOATS * 4;
    cudaFuncSetAttribute(swin_win_kernel<false>,
                         cudaFuncAttributeMaxDynamicSharedMemorySize, smem);
    cudaFuncSetAttribute(swin_win_kernel<true>,
                         cudaFuncAttributeMaxDynamicSharedMemorySize, smem);

    // Branch 0: plain stores (full coverage kills 0xAA poison)
    swin_win_kernel<false><<<8192, TPB, smem>>>(
        x, qkv_w, qkv_b, proj_w, proj_b, bn_g, bn_b, bn_m, bn_v, out, 0);
    // Branches 1 & 2: accumulate
    swin_win_kernel<true><<<16384, TPB, smem>>>(
        x, qkv_w, qkv_b, proj_w, proj_b, bn_g, bn_b, bn_m, bn_v, out, 1);
}

// round 4
// speedup vs baseline: 2.0103x; 1.1524x over previous
#include <cuda_runtime.h>

#define TPB 256
#define SCALE 0.17677669529663687f

// ---------------------------------------------------------------------------
// B=2, C=96, D=H=W=64, WS=8 -> N=64 tokens/window, HEADS=3, HD=32
// 3 branches x 8192 windows. One window per 256-thread block, fully fused.
// FFMA2 paired along reduction dim; all hot smem loads are LDS.128 with
// strides chosen so 16B-chunk step is odd mod 8 (bank-conflict floor).
// ---------------------------------------------------------------------------

union f2u { float2 f; unsigned long long u; };
union f4u { float4 v; f2u h[2]; };
__device__ __forceinline__ void fma2(f2u& d, f2u a, f2u b) {
    asm("fma.rn.f32x2 %0, %1, %2, %0;" : "+l"(d.u) : "l"(a.u), "l"(b.u));
}
__device__ __forceinline__ f4u ld4(const float* p) { f4u r; r.v = *(const float4*)p; return r; }

__device__ __forceinline__ int x_off(int br, int b, int c, int s, int p, int q) {
    int d, h, w;
    if (br == 0)      { d = s; h = p; w = q; }   // image=(b,d), spatial (h,w)
    else if (br == 1) { d = q; h = p; w = s; }   // image=(b,w), spatial (h,d)
    else              { d = p; h = s; w = q; }   // image=(b,h), spatial (d,w)
    return (((b * 96 + c) * 64 + d) * 64 + h) * 64 + w;
}

// smem layout (float offsets); total 28836 floats = 112.7 KB -> 2 CTAs/SM
#define XS   0        // [64][100] window input
#define OS   6400     // [64][100] attention output
#define QQ   12800    // [64][32]  q this head (pre-scaled)  (broadcast operand)
#define KK   14848    // [64][36]  k this head               (distinct operand)
#define VT   17152    // [32][64]  v transposed [d][tok]     (broadcast operand)
#define WST  19200    // [96][96]  staged weights [o][c]     (union with AS_)
#define AS_  19200    // [64][68]  scores
#define TB   28416    // [225]     rpb table slice this head
#define INVS 28644    // [96]
#define SHS  28740    // [96]
#define SMEM_FLOATS 28836

template<bool ATOMIC>
__global__ __launch_bounds__(TPB, 2)
void swin_win_kernel(
    const float* __restrict__ x,
    const float* __restrict__ qkv_w, const float* __restrict__ qkv_b,
    const float* __restrict__ proj_w, const float* __restrict__ proj_b,
    const float* __restrict__ rpb_table,
    const float* __restrict__ bn_g, const float* __restrict__ bn_b,
    const float* __restrict__ bn_m, const float* __restrict__ bn_v,
    float* __restrict__ out, int br_base)
{
    extern __shared__ float sm[];
    float* xs   = sm + XS;
    float* os   = sm + OS;
    float* qq   = sm + QQ;
    float* kk   = sm + KK;
    float* vt   = sm + VT;
    float* wst  = sm + WST;
    float* as_  = sm + AS_;
    float* tb   = sm + TB;
    float* invs = sm + INVS;
    float* shs  = sm + SHS;

    const int tid = threadIdx.x;
    const int bid = blockIdx.x;
    const int br  = br_base + (bid >> 13);
    const int wid = bid & 8191;
    const int g   = wid & 127;          // image index inner -> L2 line sharing
    const int win = wid >> 7;
    const int wi  = win >> 3;
    const int wj  = win & 7;
    const int b   = g >> 6;
    const int s   = g & 63;

    if (tid < 96) {
        float inv = bn_g[br * 96 + tid] * rsqrtf(bn_v[br * 96 + tid] + 1e-5f);
        invs[tid] = inv;
        shs[tid]  = bn_b[br * 96 + tid] - bn_m[br * 96 + tid] * inv;
    }

    // load window: xs[tok][c]
    for (int i = tid; i < 6144; i += TPB) {
        int c   = i >> 6;
        int tok = i & 63;
        int p = wi * 8 + (tok >> 3), q = wj * 8 + (tok & 7);
        xs[tok * 100 + c] = x[x_off(br, b, c, s, p, q)];
    }
    __syncthreads();

    // Thread tilings:
    //  GEMM1/proj: to = tid>>4 (6 outs), tn = tid&15 (tokens {tn+16i})
    //              lanes in warp differ in tn -> xs distinct (step 25 chunks),
    //              wst broadcast.
    const int to = tid >> 4;
    const int tn = tid & 15;

    // =================== per head: qkv GEMM -> attention ===================
    for (int h = 0; h < 3; ++h) {
        // stage head weights wst[u][c], u = mat*32 + dim
        for (int i = tid; i < 9216; i += TPB) {
            int u = i / 96, c = i - u * 96;
            int grow = br * 288 + (u >> 5) * 96 + h * 32 + (u & 31);
            wst[u * 96 + c] = qkv_w[grow * 96 + c];
        }
        if (tid < 225) tb[tid] = rpb_table[(br * 225 + tid) * 3 + h];
        __syncthreads();

        // ---- GEMM1: out[tok][u] = xs[tok][:] . w[u][:] + bias --------------
        {
            f2u acc[4][6];
            #pragma unroll
            for (int j = 0; j < 6; ++j) {
                int u = to * 6 + j;
                float bb = qkv_b[br * 288 + (u >> 5) * 96 + h * 32 + (u & 31)];
                #pragma unroll
                for (int i = 0; i < 4; ++i) acc[i][j].f = make_float2(bb, 0.f);
            }
            #pragma unroll 4
            for (int c = 0; c < 96; c += 4) {
                f4u av[4], wv[6];
                #pragma unroll
                for (int i = 0; i < 4; ++i) av[i] = ld4(xs + (tn + 16 * i) * 100 + c);
                #pragma unroll
                for (int j = 0; j < 6; ++j) wv[j] = ld4(wst + (to * 6 + j) * 96 + c);
                #pragma unroll
                for (int i = 0; i < 4; ++i)
                    #pragma unroll
                    for (int j = 0; j < 6; ++j) {
                        fma2(acc[i][j], av[i].h[0], wv[j].h[0]);
                        fma2(acc[i][j], av[i].h[1], wv[j].h[1]);
                    }
            }
            #pragma unroll
            for (int i = 0; i < 4; ++i) {
                int tok = tn + 16 * i;
                #pragma unroll
                for (int j = 0; j < 6; ++j) {
                    int u = to * 6 + j;
                    float r = acc[i][j].f.x + acc[i][j].f.y;
                    if (u < 32)      qq[tok * 32 + u] = r * SCALE;
                    else if (u < 64) kk[tok * 36 + (u - 32)] = r;
                    else             vt[(u - 64) * 64 + tok] = r;
                }
            }
        }
        __syncthreads();

        // ---- scores: s[n][m] = <q_n,k_m> + bias  (q pre-scaled) ------------
        // n = ng+16i (broadcast operand), m = mg+16k (distinct, step 9 chunks)
        {
            const int ng = tid >> 4;
            const int mg = tid & 15;
            f2u sacc[4][4];
            #pragma unroll
            for (int i = 0; i < 4; ++i)
                #pragma unroll
                for (int k = 0; k < 4; ++k) sacc[i][k].f = make_float2(0.f, 0.f);
            #pragma unroll 2
            for (int d = 0; d < 32; d += 4) {
                f4u qv[4], kv[4];
                #pragma unroll
                for (int i = 0; i < 4; ++i) qv[i] = ld4(qq + (ng + 16 * i) * 32 + d);
                #pragma unroll
                for (int k = 0; k < 4; ++k) kv[k] = ld4(kk + (mg + 16 * k) * 36 + d);
                #pragma unroll
                for (int i = 0; i < 4; ++i)
                    #pragma unroll
                    for (int k = 0; k < 4; ++k) {
                        fma2(sacc[i][k], qv[i].h[0], kv[k].h[0]);
                        fma2(sacc[i][k], qv[i].h[1], kv[k].h[1]);
                    }
            }
            #pragma unroll
            for (int i = 0; i < 4; ++i) {
                int n = ng + 16 * i;
                #pragma unroll
                for (int k = 0; k < 4; ++k) {
                    int m = mg + 16 * k;
                    int dy = (n >> 3) - (m >> 3) + 7;
                    int dx = (n & 7) - (m & 7) + 7;
                    as_[n * 68 + m] = sacc[i][k].f.x + sacc[i][k].f.y
                                      + tb[dy * 15 + dx];
                }
            }
        }
        __syncthreads();

        // ---- softmax: 4 lanes per row --------------------------------------
        {
            const int row  = tid >> 2;
            const int lane = tid & 3;
            float* r = as_ + row * 68 + lane * 16;
            f4u v[4];
            #pragma unroll
            for (int t = 0; t < 4; ++t) v[t] = ld4(r + t * 4);
            float mx = -1e30f;
            #pragma unroll
            for (int t = 0; t < 4; ++t) {
                mx = fmaxf(mx, fmaxf(fmaxf(v[t].v.x, v[t].v.y), fmaxf(v[t].v.z, v[t].v.w)));
            }
            mx = fmaxf(mx, __shfl_xor_sync(0xffffffff, mx, 2));
            mx = fmaxf(mx, __shfl_xor_sync(0xffffffff, mx, 1));
            float sum = 0.f;
            #pragma unroll
            for (int t = 0; t < 4; ++t) {
                v[t].v.x = __expf(v[t].v.x - mx); sum += v[t].v.x;
                v[t].v.y = __expf(v[t].v.y - mx); sum += v[t].v.y;
                v[t].v.z = __expf(v[t].v.z - mx); sum += v[t].v.z;
                v[t].v.w = __expf(v[t].v.w - mx); sum += v[t].v.w;
            }
            sum += __shfl_xor_sync(0xffffffff, sum, 2);
            sum += __shfl_xor_sync(0xffffffff, sum, 1);
            float rs = 1.f / sum;
            #pragma unroll
            for (int t = 0; t < 4; ++t) {
                v[t].v.x *= rs; v[t].v.y *= rs; v[t].v.z *= rs; v[t].v.w *= rs;
                *(float4*)(r + t * 4) = v[t].v;
            }
        }
        __syncthreads();

        // ---- out = attn @ v -> os[n][h*32+dd] ------------------------------
        // rows {ng, ng+32} distinct (step 17 chunks), vt broadcast
        {
            const int ng = tid & 31;
            const int dg = tid >> 5;
            f2u oacc[2][4];
            #pragma unroll
            for (int r2 = 0; r2 < 2; ++r2)
                #pragma unroll
                for (int jj = 0; jj < 4; ++jj) oacc[r2][jj].f = make_float2(0.f, 0.f);
            #pragma unroll 2
            for (int m = 0; m < 64; m += 4) {
                f4u a0 = ld4(as_ + ng * 68 + m);
                f4u a1 = ld4(as_ + (ng + 32) * 68 + m);
                f4u vv[4];
                #pragma unroll
                for (int jj = 0; jj < 4; ++jj) vv[jj] = ld4(vt + (dg * 4 + jj) * 64 + m);
                #pragma unroll
                for (int jj = 0; jj < 4; ++jj) {
                    fma2(oacc[0][jj], a0.h[0], vv[jj].h[0]);
                    fma2(oacc[0][jj], a0.h[1], vv[jj].h[1]);
                    fma2(oacc[1][jj], a1.h[0], vv[jj].h[0]);
                    fma2(oacc[1][jj], a1.h[1], vv[jj].h[1]);
                }
            }
            #pragma unroll
            for (int r2 = 0; r2 < 2; ++r2) {
                int n = ng + 32 * r2;
                float4 o;
                o.x = oacc[r2][0].f.x + oacc[r2][0].f.y;
                o.y = oacc[r2][1].f.x + oacc[r2][1].f.y;
                o.z = oacc[r2][2].f.x + oacc[r2][2].f.y;
                o.w = oacc[r2][3].f.x + oacc[r2][3].f.y;
                *(float4*)(os + n * 100 + h * 32 + dg * 4) = o;
            }
        }
        __syncthreads();
    }

    // =================== proj + BN + LeakyReLU + store =====================
    for (int i = tid; i < 9216; i += TPB) {
        int u = i / 96, c = i - u * 96;
        wst[u * 96 + c] = proj_w[(br * 96 + u) * 96 + c];
    }
    __syncthreads();

    {
        f2u acc[4][6];
        #pragma unroll
        for (int j = 0; j < 6; ++j) {
            float bb = proj_b[br * 96 + to * 6 + j];
            #pragma unroll
            for (int i = 0; i < 4; ++i) acc[i][j].f = make_float2(bb, 0.f);
        }
        #pragma unroll 4
        for (int c = 0; c < 96; c += 4) {
            f4u av[4], wv[6];
            #pragma unroll
            for (int i = 0; i < 4; ++i) av[i] = ld4(os + (tn + 16 * i) * 100 + c);
            #pragma unroll
            for (int j = 0; j < 6; ++j) wv[j] = ld4(wst + (to * 6 + j) * 96 + c);
            #pragma unroll
            for (int i = 0; i < 4; ++i)
                #pragma unroll
                for (int j = 0; j < 6; ++j) {
                    fma2(acc[i][j], av[i].h[0], wv[j].h[0]);
                    fma2(acc[i][j], av[i].h[1], wv[j].h[1]);
                }
        }
        #pragma unroll
        for (int i = 0; i < 4; ++i) {
            int tok = tn + 16 * i;
            int p = wi * 8 + (tok >> 3), q = wj * 8 + (tok & 7);
            #pragma unroll
            for (int j = 0; j < 6; ++j) {
                int co = to * 6 + j;
                float r  = acc[i][j].f.x + acc[i][j].f.y;
                float yn = r * invs[co] + shs[co];
                yn = (yn >= 0.f) ? yn : 0.01f * yn;
                int off = x_off(br, b, co, s, p, q);
                if (ATOMIC) atomicAdd(&out[off], yn);
                else        out[off] = yn;
            }
        }
    }
}

extern "C" void kernel_launch(void* const* d_in, const int* in_sizes, int n_in,
                              void* d_out, int out_size)
{
    (void)in_sizes; (void)n_in; (void)out_size;
    const float* x         = (const float*)d_in[0];
    const float* qkv_w     = (const float*)d_in[1];
    const float* qkv_b     = (const float*)d_in[2];
    const float* proj_w    = (const float*)d_in[3];
    const float* proj_b    = (const float*)d_in[4];
    const float* rpb_table = (const float*)d_in[5];
    const float* bn_g      = (const float*)d_in[6];
    const float* bn_b      = (const float*)d_in[7];
    const float* bn_m      = (const float*)d_in[8];
    const float* bn_v      = (const float*)d_in[9];
    float* out = (float*)d_out;

    const int smem = SMEM_FLOATS * 4;
    cudaFuncSetAttribute(swin_win_kernel<false>,
                         cudaFuncAttributeMaxDynamicSharedMemorySize, smem);
    cudaFuncSetAttribute(swin_win_kernel<true>,
                         cudaFuncAttributeMaxDynamicSharedMemorySize, smem);

    // Branch 0: plain stores (full coverage kills 0xAA poison)
    swin_win_kernel<false><<<8192, TPB, smem>>>(
        x, qkv_w, qkv_b, proj_w, proj_b, rpb_table,
        bn_g, bn_b, bn_m, bn_v, out, 0);
    // Branches 1 & 2: accumulate
    swin_win_kernel<true><<<16384, TPB, smem>>>(
        x, qkv_w, qkv_b, proj_w, proj_b, rpb_table,
        bn_g, bn_b, bn_m, bn_v, out, 1);
}